// round 1
// baseline (speedup 1.0000x reference)
#include <cuda_runtime.h>
#include <math.h>

#define EMB 1024
#define NH 16
#define HD 64
#define BB 4
#define TT 2048
#define ROWS (BB * TT) /* 8192 */

// Scratch (allocation-free rule: __device__ globals)
__device__ float g_qp[ROWS * EMB]; // quantum(x@Wq+bq) -> acts as KEY
__device__ float g_kp[ROWS * EMB]; // quantum(x@Wk+bk) -> acts as QUERY
__device__ float g_vp[ROWS * EMB]; // x@Wv+bv
__device__ float g_ao[ROWS * EMB]; // attention output (combined heads)

// ---------------------------------------------------------------------------
// SGEMM: C[M,N] = A[M,K] @ W[K,N] + bias   (M=8192, N=K=1024)
// 128x128 block, BK=8, 8x8 microtile, 256 threads
// ---------------------------------------------------------------------------
__global__ __launch_bounds__(256) void sgemm_bias(
    const float* __restrict__ A, const float* __restrict__ W,
    const float* __restrict__ bias, float* __restrict__ C)
{
    const int N = EMB, K = EMB;
    __shared__ float As[8][128];
    __shared__ float Bs[8][128];

    int tid = threadIdx.x;
    int bx = blockIdx.x, by = blockIdx.y;
    int tcol = tid & 15, trow = tid >> 4;

    int aRow = tid >> 1;           // 0..127
    int aCol = (tid & 1) * 4;      // 0 or 4
    int bRow = tid >> 5;           // 0..7
    int bCol = (tid & 31) * 4;     // 0..124

    const float* Ab = A + (size_t)(by * 128) * K;
    const float* Wb = W + bx * 128;

    float acc[8][8];
#pragma unroll
    for (int i = 0; i < 8; i++)
#pragma unroll
        for (int j = 0; j < 8; j++) acc[i][j] = 0.f;

    for (int k0 = 0; k0 < K; k0 += 8) {
        float4 a4 = *(const float4*)(Ab + (size_t)aRow * K + k0 + aCol);
        As[aCol + 0][aRow] = a4.x;
        As[aCol + 1][aRow] = a4.y;
        As[aCol + 2][aRow] = a4.z;
        As[aCol + 3][aRow] = a4.w;
        *(float4*)&Bs[bRow][bCol] =
            *(const float4*)(Wb + (size_t)(k0 + bRow) * N + bCol);
        __syncthreads();

#pragma unroll
        for (int kk = 0; kk < 8; kk++) {
            float4 t0 = *(const float4*)&As[kk][trow * 8];
            float4 t1 = *(const float4*)&As[kk][trow * 8 + 4];
            float4 u0 = *(const float4*)&Bs[kk][tcol * 8];
            float4 u1 = *(const float4*)&Bs[kk][tcol * 8 + 4];
            float rm[8], rn[8];
            rm[0] = t0.x; rm[1] = t0.y; rm[2] = t0.z; rm[3] = t0.w;
            rm[4] = t1.x; rm[5] = t1.y; rm[6] = t1.z; rm[7] = t1.w;
            rn[0] = u0.x; rn[1] = u0.y; rn[2] = u0.z; rn[3] = u0.w;
            rn[4] = u1.x; rn[5] = u1.y; rn[6] = u1.z; rn[7] = u1.w;
#pragma unroll
            for (int i = 0; i < 8; i++)
#pragma unroll
                for (int j = 0; j < 8; j++)
                    acc[i][j] = fmaf(rm[i], rn[j], acc[i][j]);
        }
        __syncthreads();
    }

#pragma unroll
    for (int i = 0; i < 8; i++) {
        int r = by * 128 + trow * 8 + i;
#pragma unroll
        for (int j = 0; j < 8; j += 4) {
            int c = bx * 128 + tcol * 8 + j;
            float4 o;
            o.x = acc[i][j + 0] + bias[c + 0];
            o.y = acc[i][j + 1] + bias[c + 1];
            o.z = acc[i][j + 2] + bias[c + 2];
            o.w = acc[i][j + 3] + bias[c + 3];
            *(float4*)&C[(size_t)r * N + c] = o;
        }
    }
}

// ---------------------------------------------------------------------------
// quantum_layer: in-place cumprod(cos(x)) along rows of length 1024.
// One block per row, 256 threads x 4 elements, block-level product scan.
// ---------------------------------------------------------------------------
__global__ __launch_bounds__(256) void quantum_scan(float* __restrict__ data)
{
    __shared__ float s[256];
    int row = blockIdx.x;
    float4* p = (float4*)(data + (size_t)row * EMB);
    int t = threadIdx.x;

    float4 v = p[t];
    float c0 = cosf(v.x), c1 = cosf(v.y), c2 = cosf(v.z), c3 = cosf(v.w);
    float p0 = c0;
    float p1 = p0 * c1;
    float p2 = p1 * c2;
    float p3 = p2 * c3;

    s[t] = p3;
    __syncthreads();
    for (int off = 1; off < 256; off <<= 1) {
        float o = (t >= off) ? s[t - off] : 1.0f;
        __syncthreads();
        s[t] *= o;
        __syncthreads();
    }
    float pref = (t > 0) ? s[t - 1] : 1.0f;
    p[t] = make_float4(pref * p0, pref * p1, pref * p2, pref * p3);
}

// ---------------------------------------------------------------------------
// Flash attention, fp32. D=64. Block = one (b,h) x 64-query tile, 256 threads.
// Qp: query tensor (B,T,E) with head h in cols [64h,64h+64)
// Us buffer holds K^T during S-gemm, then reused for P.
// ---------------------------------------------------------------------------
__global__ __launch_bounds__(256) void flash_attn(
    const float* __restrict__ Qp, const float* __restrict__ Kp,
    const float* __restrict__ Vp, float* __restrict__ Op)
{
    __shared__ float Qs[64][64]; // Qs[r][d]
    __shared__ float Us[64][64]; // K^T: Us[d][c]; later P: Us[r][k]
    __shared__ float Vs[64][64]; // Vs[k][d]

    int tid = threadIdx.x;
    int tx = tid & 15, ty = tid >> 4;
    int bh = blockIdx.y;
    int b = bh >> 4, h = bh & 15;
    int q0 = blockIdx.x * 64;
    size_t base = (size_t)b * TT * EMB + h * HD;

    // Load Q tile (coalesced: consecutive threads -> consecutive float4)
#pragma unroll
    for (int it = 0; it < 4; ++it) {
        int idx = tid + it * 256;
        int r = idx >> 4, c4 = (idx & 15) * 4;
        *(float4*)&Qs[r][c4] =
            *(const float4*)(Qp + base + (size_t)(q0 + r) * EMB + c4);
    }

    float m[4], l[4], acc[4][4];
#pragma unroll
    for (int i = 0; i < 4; i++) {
        m[i] = -INFINITY;
        l[i] = 0.f;
#pragma unroll
        for (int j = 0; j < 4; j++) acc[i][j] = 0.f;
    }

    for (int kt = 0; kt < TT / 64; ++kt) {
        __syncthreads(); // previous tile's reads of Us/Vs complete
#pragma unroll
        for (int it = 0; it < 4; ++it) {
            int idx = tid + it * 256;
            int r = idx >> 4, c4 = (idx & 15) * 4;
            const float* ksrc = Kp + base + (size_t)(kt * 64 + r) * EMB + c4;
            const float* vsrc = Vp + base + (size_t)(kt * 64 + r) * EMB + c4;
            float4 k4 = *(const float4*)ksrc;
            Us[c4 + 0][r] = k4.x;
            Us[c4 + 1][r] = k4.y;
            Us[c4 + 2][r] = k4.z;
            Us[c4 + 3][r] = k4.w;
            *(float4*)&Vs[r][c4] = *(const float4*)vsrc;
        }
        __syncthreads();

        // S = Q @ K^T  (rows = ty*4+i, cols = tx*4+j)
        float sv[4][4];
#pragma unroll
        for (int i = 0; i < 4; i++)
#pragma unroll
            for (int j = 0; j < 4; j++) sv[i][j] = 0.f;

#pragma unroll 16
        for (int d = 0; d < 64; ++d) {
            float4 kx = *(const float4*)&Us[d][tx * 4];
            float qa = Qs[ty * 4 + 0][d];
            float qb = Qs[ty * 4 + 1][d];
            float qc = Qs[ty * 4 + 2][d];
            float qd = Qs[ty * 4 + 3][d];
            sv[0][0] = fmaf(qa, kx.x, sv[0][0]); sv[0][1] = fmaf(qa, kx.y, sv[0][1]);
            sv[0][2] = fmaf(qa, kx.z, sv[0][2]); sv[0][3] = fmaf(qa, kx.w, sv[0][3]);
            sv[1][0] = fmaf(qb, kx.x, sv[1][0]); sv[1][1] = fmaf(qb, kx.y, sv[1][1]);
            sv[1][2] = fmaf(qb, kx.z, sv[1][2]); sv[1][3] = fmaf(qb, kx.w, sv[1][3]);
            sv[2][0] = fmaf(qc, kx.x, sv[2][0]); sv[2][1] = fmaf(qc, kx.y, sv[2][1]);
            sv[2][2] = fmaf(qc, kx.z, sv[2][2]); sv[2][3] = fmaf(qc, kx.w, sv[2][3]);
            sv[3][0] = fmaf(qd, kx.x, sv[3][0]); sv[3][1] = fmaf(qd, kx.y, sv[3][1]);
            sv[3][2] = fmaf(qd, kx.z, sv[3][2]); sv[3][3] = fmaf(qd, kx.w, sv[3][3]);
        }

        // Online softmax per row (row spread over 16 lanes: shfl_xor<16)
        float pmat[4][4];
#pragma unroll
        for (int i = 0; i < 4; i++) {
            float rmax = -INFINITY;
#pragma unroll
            for (int j = 0; j < 4; j++) {
                sv[i][j] *= 0.125f; // 1/sqrt(64)
                rmax = fmaxf(rmax, sv[i][j]);
            }
#pragma unroll
            for (int off = 1; off < 16; off <<= 1)
                rmax = fmaxf(rmax, __shfl_xor_sync(0xffffffffu, rmax, off));
            float mn = fmaxf(m[i], rmax);
            float corr = __expf(m[i] - mn);
            float rsum = 0.f;
#pragma unroll
            for (int j = 0; j < 4; j++) {
                pmat[i][j] = __expf(sv[i][j] - mn);
                rsum += pmat[i][j];
            }
#pragma unroll
            for (int off = 1; off < 16; off <<= 1)
                rsum += __shfl_xor_sync(0xffffffffu, rsum, off);
            l[i] = l[i] * corr + rsum;
            m[i] = mn;
#pragma unroll
            for (int j = 0; j < 4; j++) acc[i][j] *= corr;
        }

        __syncthreads(); // all reads of Us (K^T) done before reuse for P
#pragma unroll
        for (int i = 0; i < 4; i++) {
            Us[ty * 4 + i][tx * 4 + 0] = pmat[i][0];
            Us[ty * 4 + i][tx * 4 + 1] = pmat[i][1];
            Us[ty * 4 + i][tx * 4 + 2] = pmat[i][2];
            Us[ty * 4 + i][tx * 4 + 3] = pmat[i][3];
        }
        __syncthreads();

        // acc += P @ V  (cols now = head dim tx*4+j)
#pragma unroll 16
        for (int k = 0; k < 64; ++k) {
            float4 vx = *(const float4*)&Vs[k][tx * 4];
            float pa = Us[ty * 4 + 0][k];
            float pb = Us[ty * 4 + 1][k];
            float pc = Us[ty * 4 + 2][k];
            float pd = Us[ty * 4 + 3][k];
            acc[0][0] = fmaf(pa, vx.x, acc[0][0]); acc[0][1] = fmaf(pa, vx.y, acc[0][1]);
            acc[0][2] = fmaf(pa, vx.z, acc[0][2]); acc[0][3] = fmaf(pa, vx.w, acc[0][3]);
            acc[1][0] = fmaf(pb, vx.x, acc[1][0]); acc[1][1] = fmaf(pb, vx.y, acc[1][1]);
            acc[1][2] = fmaf(pb, vx.z, acc[1][2]); acc[1][3] = fmaf(pb, vx.w, acc[1][3]);
            acc[2][0] = fmaf(pc, vx.x, acc[2][0]); acc[2][1] = fmaf(pc, vx.y, acc[2][1]);
            acc[2][2] = fmaf(pc, vx.z, acc[2][2]); acc[2][3] = fmaf(pc, vx.w, acc[2][3]);
            acc[3][0] = fmaf(pd, vx.x, acc[3][0]); acc[3][1] = fmaf(pd, vx.y, acc[3][1]);
            acc[3][2] = fmaf(pd, vx.z, acc[3][2]); acc[3][3] = fmaf(pd, vx.w, acc[3][3]);
        }
    }

    // Epilogue: normalize and write combined-heads layout (B,T,E)
#pragma unroll
    for (int i = 0; i < 4; i++) {
        float inv = 1.0f / l[i];
        size_t off = base + (size_t)(q0 + ty * 4 + i) * EMB + tx * 4;
        float4 o = make_float4(acc[i][0] * inv, acc[i][1] * inv,
                               acc[i][2] * inv, acc[i][3] * inv);
        *(float4*)&Op[off] = o;
    }
}

// ---------------------------------------------------------------------------
extern "C" void kernel_launch(void* const* d_in, const int* in_sizes, int n_in,
                              void* d_out, int out_size)
{
    const float* x  = (const float*)d_in[0];
    const float* Wq = (const float*)d_in[1];
    const float* bq = (const float*)d_in[2];
    const float* Wk = (const float*)d_in[3];
    const float* bk = (const float*)d_in[4];
    const float* Wv = (const float*)d_in[5];
    const float* bv = (const float*)d_in[6];
    const float* Wo = (const float*)d_in[7];
    const float* bo = (const float*)d_in[8];
    float* out = (float*)d_out;

    float *qp, *kp, *vp, *ao;
    cudaGetSymbolAddress((void**)&qp, g_qp);
    cudaGetSymbolAddress((void**)&kp, g_kp);
    cudaGetSymbolAddress((void**)&vp, g_vp);
    cudaGetSymbolAddress((void**)&ao, g_ao);

    dim3 gg(EMB / 128, ROWS / 128); // (8, 64)
    sgemm_bias<<<gg, 256>>>(x, Wq, bq, qp);
    sgemm_bias<<<gg, 256>>>(x, Wk, bk, kp);
    sgemm_bias<<<gg, 256>>>(x, Wv, bv, vp);

    quantum_scan<<<ROWS, 256>>>(qp);
    quantum_scan<<<ROWS, 256>>>(kp);

    // Role swap per reference: query = quantum(k-proj), key = quantum(q-proj)
    dim3 ga(TT / 64, BB * NH); // (32, 64)
    flash_attn<<<ga, 256>>>(kp, qp, vp, ao);

    sgemm_bias<<<gg, 256>>>(ao, Wo, bo, out);
}

// round 3
// speedup vs baseline: 1.3380x; 1.3380x over previous
#include <cuda_runtime.h>
#include <cuda_bf16.h>
#include <cstdint>
#include <math.h>

#define EMB 1024
#define NH 16
#define HD 64
#define BB 4
#define TT 2048
#define ROWS (BB * TT) /* 8192 */

// ---------------- scratch (__device__ globals; no allocation allowed) -------
__device__ float g_qp[ROWS * EMB]; // quantum(x@Wq+bq) -> acts as KEY
__device__ float g_kp[ROWS * EMB]; // quantum(x@Wk+bk) -> acts as QUERY
__device__ float g_vp[ROWS * EMB]; // x@Wv+bv
__device__ float g_ao[ROWS * EMB]; // attention output (combined heads)

__device__ __nv_bfloat16 g_xh[ROWS * EMB], g_xl[ROWS * EMB];   // x split
__device__ __nv_bfloat16 g_aoh[ROWS * EMB], g_aol[ROWS * EMB]; // ao split
__device__ __nv_bfloat16 g_wqh[EMB * EMB], g_wql[EMB * EMB];   // W^T splits
__device__ __nv_bfloat16 g_wkh[EMB * EMB], g_wkl[EMB * EMB];
__device__ __nv_bfloat16 g_wvh[EMB * EMB], g_wvl[EMB * EMB];
__device__ __nv_bfloat16 g_woh[EMB * EMB], g_wol[EMB * EMB];

// ---------------- warp-mma helpers (compute_103-legal) ----------------------
__device__ __forceinline__ uint32_t smem_u32(const void* p) {
    uint32_t a;
    asm("{ .reg .u64 t; cvta.to.shared.u64 t, %1; cvt.u32.u64 %0, t; }"
        : "=r"(a) : "l"(p));
    return a;
}

__device__ __forceinline__ void ldsm4(uint32_t* r, uint32_t addr) {
    asm volatile("ldmatrix.sync.aligned.m8n8.x4.shared.b16 {%0,%1,%2,%3}, [%4];"
                 : "=r"(r[0]), "=r"(r[1]), "=r"(r[2]), "=r"(r[3]) : "r"(addr));
}

__device__ __forceinline__ void mma_bf16(float* d, const uint32_t* a,
                                         uint32_t b0, uint32_t b1) {
    asm volatile(
        "mma.sync.aligned.m16n8k16.row.col.f32.bf16.bf16.f32 "
        "{%0,%1,%2,%3}, {%4,%5,%6,%7}, {%8,%9}, {%0,%1,%2,%3};"
        : "+f"(d[0]), "+f"(d[1]), "+f"(d[2]), "+f"(d[3])
        : "r"(a[0]), "r"(a[1]), "r"(a[2]), "r"(a[3]), "r"(b0), "r"(b1));
}

// ---------------------------------------------------------------------------
// split fp32 -> bf16 hi/lo
// ---------------------------------------------------------------------------
__global__ __launch_bounds__(256) void split_bf16(
    const float* __restrict__ src,
    __nv_bfloat16* __restrict__ hi, __nv_bfloat16* __restrict__ lo, int n4)
{
    int i = blockIdx.x * blockDim.x + threadIdx.x;
    if (i >= n4) return;
    float4 v = ((const float4*)src)[i];
    __nv_bfloat16 h0 = __float2bfloat16(v.x), h1 = __float2bfloat16(v.y);
    __nv_bfloat16 h2 = __float2bfloat16(v.z), h3 = __float2bfloat16(v.w);
    __nv_bfloat16 l0 = __float2bfloat16(v.x - __bfloat162float(h0));
    __nv_bfloat16 l1 = __float2bfloat16(v.y - __bfloat162float(h1));
    __nv_bfloat16 l2 = __float2bfloat16(v.z - __bfloat162float(h2));
    __nv_bfloat16 l3 = __float2bfloat16(v.w - __bfloat162float(h3));
    __nv_bfloat162* hp = (__nv_bfloat162*)hi;
    __nv_bfloat162* lp = (__nv_bfloat162*)lo;
    hp[i * 2 + 0] = __halves2bfloat162(h0, h1);
    hp[i * 2 + 1] = __halves2bfloat162(h2, h3);
    lp[i * 2 + 0] = __halves2bfloat162(l0, l1);
    lp[i * 2 + 1] = __halves2bfloat162(l2, l3);
}

// ---------------------------------------------------------------------------
// transpose + split: Wt[n][k] = W[k][n] as bf16 hi/lo  (1024x1024)
// ---------------------------------------------------------------------------
__global__ __launch_bounds__(256) void tsplit_bf16(
    const float* __restrict__ W,
    __nv_bfloat16* __restrict__ th, __nv_bfloat16* __restrict__ tl)
{
    __shared__ float s[32][33];
    int tx = threadIdx.x, ty = threadIdx.y; // (32, 8)
    int n0 = blockIdx.x * 32, k0 = blockIdx.y * 32;
#pragma unroll
    for (int j = 0; j < 4; j++)
        s[ty + 8 * j][tx] = W[(size_t)(k0 + ty + 8 * j) * EMB + n0 + tx];
    __syncthreads();
#pragma unroll
    for (int j = 0; j < 4; j++) {
        int n = n0 + ty + 8 * j, k = k0 + tx;
        float v = s[tx][ty + 8 * j];
        __nv_bfloat16 h = __float2bfloat16(v);
        th[(size_t)n * EMB + k] = h;
        tl[(size_t)n * EMB + k] = __float2bfloat16(v - __bfloat162float(h));
    }
}

// ---------------------------------------------------------------------------
// Tensor-core GEMM via mma.sync bf16 hi/lo split:
// C[M,N] = (Ah+Al)@(Bh+Bl)^T + bias, M=8192, N=K=1024.
// A: [M,K] row-major bf16, B: [N,K] row-major bf16 (pre-transposed W).
// 128x128 CTA tile, 8 warps (2x4, warp tile 64x32), K-chunk 32, dbl-buffered.
// SMEM rows padded to 40 bf16 (80 B): 80*i mod 128 distinct for i=0..7 ->
// conflict-free ldmatrix without swizzle.
// ---------------------------------------------------------------------------
#define SROW 40                 /* bf16 elems per smem row (80 B) */
#define TILE_B (128 * SROW * 2) /* 10240 bytes per tile */
#define STAGE_B (4 * TILE_B)    /* Ah, Al, Bh, Bl */
#define GSMEM_TOTAL (2 * STAGE_B)

__global__ __launch_bounds__(256) void gemm_tc(
    const __nv_bfloat16* __restrict__ Ah, const __nv_bfloat16* __restrict__ Al,
    const __nv_bfloat16* __restrict__ Bh, const __nv_bfloat16* __restrict__ Bl,
    const float* __restrict__ bias, float* __restrict__ C)
{
    extern __shared__ char smem[];
    const int tid = threadIdx.x, wid = tid >> 5, L = tid & 31;
    const int bx = blockIdx.x, by = blockIdx.y;
    const uint32_t sb = smem_u32(smem);

    const int warp_m = (wid >> 2) * 64;
    const int warp_n = (wid & 3) * 32;

    // per-lane ldmatrix byte offsets (within a tile)
    const uint32_t a_off = (uint32_t)(warp_m + (L & 15)) * 80 + (L >> 4) * 16;
    const uint32_t b_off =
        (uint32_t)(warp_n + (L >> 4) * 8 + (L & 7)) * 80 + ((L >> 3) & 1) * 16;

    // global load mapping: idx = tid + u*256; r = idx>>2 (0..127), c = idx&3
    const int lr = tid >> 2, lc = tid & 3;
    const __nv_bfloat16* gA[2] = {Ah + (size_t)(by * 128 + lr) * EMB + lc * 8,
                                  Al + (size_t)(by * 128 + lr) * EMB + lc * 8};
    const __nv_bfloat16* gB[2] = {Bh + (size_t)(bx * 128 + lr) * EMB + lc * 8,
                                  Bl + (size_t)(bx * 128 + lr) * EMB + lc * 8};
    const uint32_t s_off0 = (uint32_t)lr * 80 + lc * 16;        // row lr
    const uint32_t s_off1 = (uint32_t)(lr + 64) * 80 + lc * 16; // row lr+64

    float acc[4][4][4];
#pragma unroll
    for (int mt = 0; mt < 4; mt++)
#pragma unroll
        for (int nt = 0; nt < 4; nt++)
#pragma unroll
            for (int j = 0; j < 4; j++) acc[mt][nt][j] = 0.f;

    // preload chunk 0 into stage 0
#pragma unroll
    for (int t = 0; t < 2; t++) {
        char* dst = smem + t * TILE_B;
        *(uint4*)(dst + s_off0) = *(const uint4*)(gA[t]);
        *(uint4*)(dst + s_off1) = *(const uint4*)(gA[t] + 64 * EMB);
        char* dstB = smem + (2 + t) * TILE_B;
        *(uint4*)(dstB + s_off0) = *(const uint4*)(gB[t]);
        *(uint4*)(dstB + s_off1) = *(const uint4*)(gB[t] + 64 * EMB);
    }
    __syncthreads();

    const int NC = EMB / 32; // 32 chunks
    uint4 stg[8];

    for (int kc = 0; kc < NC; ++kc) {
        const int cur = kc & 1;
        // issue next chunk's global loads early (overlap with mma)
        if (kc + 1 < NC) {
            const int k0 = (kc + 1) * 32;
#pragma unroll
            for (int t = 0; t < 2; t++) {
                stg[t * 2 + 0] = *(const uint4*)(gA[t] + k0);
                stg[t * 2 + 1] = *(const uint4*)(gA[t] + 64 * EMB + k0);
                stg[4 + t * 2 + 0] = *(const uint4*)(gB[t] + k0);
                stg[4 + t * 2 + 1] = *(const uint4*)(gB[t] + 64 * EMB + k0);
            }
        }

        const uint32_t st = sb + cur * STAGE_B;
#pragma unroll
        for (int ks = 0; ks < 2; ++ks) {
            uint32_t afh[4][4], afl[4][4], bfh[2][4], bfl[2][4];
#pragma unroll
            for (int mt = 0; mt < 4; mt++) {
                uint32_t ad = st + a_off + mt * (16 * 80) + ks * 32;
                ldsm4(afh[mt], ad);            // Ah tile
                ldsm4(afl[mt], ad + TILE_B);   // Al tile
            }
#pragma unroll
            for (int np = 0; np < 2; np++) {
                uint32_t bd = st + 2 * TILE_B + b_off + np * (16 * 80) + ks * 32;
                ldsm4(bfh[np], bd);            // Bh tile
                ldsm4(bfl[np], bd + TILE_B);   // Bl tile
            }
#pragma unroll
            for (int mt = 0; mt < 4; mt++)
#pragma unroll
                for (int np = 0; np < 2; np++) {
                    mma_bf16(acc[mt][np * 2 + 0], afh[mt], bfh[np][0], bfh[np][1]);
                    mma_bf16(acc[mt][np * 2 + 0], afh[mt], bfl[np][0], bfl[np][1]);
                    mma_bf16(acc[mt][np * 2 + 0], afl[mt], bfh[np][0], bfh[np][1]);
                    mma_bf16(acc[mt][np * 2 + 1], afh[mt], bfh[np][2], bfh[np][3]);
                    mma_bf16(acc[mt][np * 2 + 1], afh[mt], bfl[np][2], bfl[np][3]);
                    mma_bf16(acc[mt][np * 2 + 1], afl[mt], bfh[np][2], bfh[np][3]);
                }
        }

        if (kc + 1 < NC) {
            __syncthreads(); // everyone done reading the OTHER stage
            char* nb = smem + (cur ^ 1) * STAGE_B;
#pragma unroll
            for (int t = 0; t < 2; t++) {
                *(uint4*)(nb + t * TILE_B + s_off0) = stg[t * 2 + 0];
                *(uint4*)(nb + t * TILE_B + s_off1) = stg[t * 2 + 1];
                *(uint4*)(nb + (2 + t) * TILE_B + s_off0) = stg[4 + t * 2 + 0];
                *(uint4*)(nb + (2 + t) * TILE_B + s_off1) = stg[4 + t * 2 + 1];
            }
            __syncthreads();
        }
    }

    // epilogue: fragment layout c0,c1 -> row t/4, cols 2(t%4)+{0,1}; c2,c3 row+8
    const int qr = L >> 2, qc = (L & 3) * 2;
#pragma unroll
    for (int mt = 0; mt < 4; mt++) {
#pragma unroll
        for (int nt = 0; nt < 4; nt++) {
            int col = bx * 128 + warp_n + nt * 8 + qc;
            float b0 = bias[col], b1 = bias[col + 1];
            int r0 = by * 128 + warp_m + mt * 16 + qr;
            float2 o0 = make_float2(acc[mt][nt][0] + b0, acc[mt][nt][1] + b1);
            float2 o1 = make_float2(acc[mt][nt][2] + b0, acc[mt][nt][3] + b1);
            *(float2*)&C[(size_t)r0 * EMB + col] = o0;
            *(float2*)&C[(size_t)(r0 + 8) * EMB + col] = o1;
        }
    }
}

// ---------------------------------------------------------------------------
// quantum_layer: in-place cumprod(cos(x)) along rows of length 1024.
// ---------------------------------------------------------------------------
__global__ __launch_bounds__(256) void quantum_scan(float* __restrict__ data)
{
    __shared__ float s[256];
    int row = blockIdx.x;
    float4* p = (float4*)(data + (size_t)row * EMB);
    int t = threadIdx.x;

    float4 v = p[t];
    float c0 = cosf(v.x), c1 = cosf(v.y), c2 = cosf(v.z), c3 = cosf(v.w);
    float p0 = c0;
    float p1 = p0 * c1;
    float p2 = p1 * c2;
    float p3 = p2 * c3;

    s[t] = p3;
    __syncthreads();
    for (int off = 1; off < 256; off <<= 1) {
        float o = (t >= off) ? s[t - off] : 1.0f;
        __syncthreads();
        s[t] *= o;
        __syncthreads();
    }
    float pref = (t > 0) ? s[t - 1] : 1.0f;
    p[t] = make_float4(pref * p0, pref * p1, pref * p2, pref * p3);
}

// ---------------------------------------------------------------------------
// Flash attention, fp32 (unchanged — tensorize in next round)
// ---------------------------------------------------------------------------
__global__ __launch_bounds__(256) void flash_attn(
    const float* __restrict__ Qp, const float* __restrict__ Kp,
    const float* __restrict__ Vp, float* __restrict__ Op)
{
    __shared__ float Qs[64][64];
    __shared__ float Us[64][64];
    __shared__ float Vs[64][64];

    int tid = threadIdx.x;
    int tx = tid & 15, ty = tid >> 4;
    int bh = blockIdx.y;
    int b = bh >> 4, h = bh & 15;
    int q0 = blockIdx.x * 64;
    size_t base = (size_t)b * TT * EMB + h * HD;

#pragma unroll
    for (int it = 0; it < 4; ++it) {
        int idx = tid + it * 256;
        int r = idx >> 4, c4 = (idx & 15) * 4;
        *(float4*)&Qs[r][c4] =
            *(const float4*)(Qp + base + (size_t)(q0 + r) * EMB + c4);
    }

    float m[4], l[4], acc[4][4];
#pragma unroll
    for (int i = 0; i < 4; i++) {
        m[i] = -INFINITY;
        l[i] = 0.f;
#pragma unroll
        for (int j = 0; j < 4; j++) acc[i][j] = 0.f;
    }

    for (int kt = 0; kt < TT / 64; ++kt) {
        __syncthreads();
#pragma unroll
        for (int it = 0; it < 4; ++it) {
            int idx = tid + it * 256;
            int r = idx >> 4, c4 = (idx & 15) * 4;
            const float* ksrc = Kp + base + (size_t)(kt * 64 + r) * EMB + c4;
            const float* vsrc = Vp + base + (size_t)(kt * 64 + r) * EMB + c4;
            float4 k4 = *(const float4*)ksrc;
            Us[c4 + 0][r] = k4.x;
            Us[c4 + 1][r] = k4.y;
            Us[c4 + 2][r] = k4.z;
            Us[c4 + 3][r] = k4.w;
            *(float4*)&Vs[r][c4] = *(const float4*)vsrc;
        }
        __syncthreads();

        float sv[4][4];
#pragma unroll
        for (int i = 0; i < 4; i++)
#pragma unroll
            for (int j = 0; j < 4; j++) sv[i][j] = 0.f;

#pragma unroll 16
        for (int d = 0; d < 64; ++d) {
            float4 kx = *(const float4*)&Us[d][tx * 4];
            float qa = Qs[ty * 4 + 0][d];
            float qb = Qs[ty * 4 + 1][d];
            float qc = Qs[ty * 4 + 2][d];
            float qd = Qs[ty * 4 + 3][d];
            sv[0][0] = fmaf(qa, kx.x, sv[0][0]); sv[0][1] = fmaf(qa, kx.y, sv[0][1]);
            sv[0][2] = fmaf(qa, kx.z, sv[0][2]); sv[0][3] = fmaf(qa, kx.w, sv[0][3]);
            sv[1][0] = fmaf(qb, kx.x, sv[1][0]); sv[1][1] = fmaf(qb, kx.y, sv[1][1]);
            sv[1][2] = fmaf(qb, kx.z, sv[1][2]); sv[1][3] = fmaf(qb, kx.w, sv[1][3]);
            sv[2][0] = fmaf(qc, kx.x, sv[2][0]); sv[2][1] = fmaf(qc, kx.y, sv[2][1]);
            sv[2][2] = fmaf(qc, kx.z, sv[2][2]); sv[2][3] = fmaf(qc, kx.w, sv[2][3]);
            sv[3][0] = fmaf(qd, kx.x, sv[3][0]); sv[3][1] = fmaf(qd, kx.y, sv[3][1]);
            sv[3][2] = fmaf(qd, kx.z, sv[3][2]); sv[3][3] = fmaf(qd, kx.w, sv[3][3]);
        }

        float pmat[4][4];
#pragma unroll
        for (int i = 0; i < 4; i++) {
            float rmax = -INFINITY;
#pragma unroll
            for (int j = 0; j < 4; j++) {
                sv[i][j] *= 0.125f;
                rmax = fmaxf(rmax, sv[i][j]);
            }
#pragma unroll
            for (int off = 1; off < 16; off <<= 1)
                rmax = fmaxf(rmax, __shfl_xor_sync(0xffffffffu, rmax, off));
            float mn = fmaxf(m[i], rmax);
            float corr = __expf(m[i] - mn);
            float rsum = 0.f;
#pragma unroll
            for (int j = 0; j < 4; j++) {
                pmat[i][j] = __expf(sv[i][j] - mn);
                rsum += pmat[i][j];
            }
#pragma unroll
            for (int off = 1; off < 16; off <<= 1)
                rsum += __shfl_xor_sync(0xffffffffu, rsum, off);
            l[i] = l[i] * corr + rsum;
            m[i] = mn;
#pragma unroll
            for (int j = 0; j < 4; j++) acc[i][j] *= corr;
        }

        __syncthreads();
#pragma unroll
        for (int i = 0; i < 4; i++) {
            Us[ty * 4 + i][tx * 4 + 0] = pmat[i][0];
            Us[ty * 4 + i][tx * 4 + 1] = pmat[i][1];
            Us[ty * 4 + i][tx * 4 + 2] = pmat[i][2];
            Us[ty * 4 + i][tx * 4 + 3] = pmat[i][3];
        }
        __syncthreads();

#pragma unroll 16
        for (int k = 0; k < 64; ++k) {
            float4 vx = *(const float4*)&Vs[k][tx * 4];
            float pa = Us[ty * 4 + 0][k];
            float pb = Us[ty * 4 + 1][k];
            float pc = Us[ty * 4 + 2][k];
            float pd = Us[ty * 4 + 3][k];
            acc[0][0] = fmaf(pa, vx.x, acc[0][0]); acc[0][1] = fmaf(pa, vx.y, acc[0][1]);
            acc[0][2] = fmaf(pa, vx.z, acc[0][2]); acc[0][3] = fmaf(pa, vx.w, acc[0][3]);
            acc[1][0] = fmaf(pb, vx.x, acc[1][0]); acc[1][1] = fmaf(pb, vx.y, acc[1][1]);
            acc[1][2] = fmaf(pb, vx.z, acc[1][2]); acc[1][3] = fmaf(pb, vx.w, acc[1][3]);
            acc[2][0] = fmaf(pc, vx.x, acc[2][0]); acc[2][1] = fmaf(pc, vx.y, acc[2][1]);
            acc[2][2] = fmaf(pc, vx.z, acc[2][2]); acc[2][3] = fmaf(pc, vx.w, acc[2][3]);
            acc[3][0] = fmaf(pd, vx.x, acc[3][0]); acc[3][1] = fmaf(pd, vx.y, acc[3][1]);
            acc[3][2] = fmaf(pd, vx.z, acc[3][2]); acc[3][3] = fmaf(pd, vx.w, acc[3][3]);
        }
    }

#pragma unroll
    for (int i = 0; i < 4; i++) {
        float inv = 1.0f / l[i];
        size_t off = base + (size_t)(q0 + ty * 4 + i) * EMB + tx * 4;
        float4 o = make_float4(acc[i][0] * inv, acc[i][1] * inv,
                               acc[i][2] * inv, acc[i][3] * inv);
        *(float4*)&Op[off] = o;
    }
}

// ---------------------------------------------------------------------------
extern "C" void kernel_launch(void* const* d_in, const int* in_sizes, int n_in,
                              void* d_out, int out_size)
{
    const float* x  = (const float*)d_in[0];
    const float* Wq = (const float*)d_in[1];
    const float* bq = (const float*)d_in[2];
    const float* Wk = (const float*)d_in[3];
    const float* bk = (const float*)d_in[4];
    const float* Wv = (const float*)d_in[5];
    const float* bv = (const float*)d_in[6];
    const float* Wo = (const float*)d_in[7];
    const float* bo = (const float*)d_in[8];
    float* out = (float*)d_out;

    float *qp, *kp, *vp, *ao;
    cudaGetSymbolAddress((void**)&qp, g_qp);
    cudaGetSymbolAddress((void**)&kp, g_kp);
    cudaGetSymbolAddress((void**)&vp, g_vp);
    cudaGetSymbolAddress((void**)&ao, g_ao);

    __nv_bfloat16 *xh, *xl, *aoh, *aol;
    __nv_bfloat16 *wqh, *wql, *wkh, *wkl, *wvh, *wvl, *woh, *wol;
    cudaGetSymbolAddress((void**)&xh, g_xh);
    cudaGetSymbolAddress((void**)&xl, g_xl);
    cudaGetSymbolAddress((void**)&aoh, g_aoh);
    cudaGetSymbolAddress((void**)&aol, g_aol);
    cudaGetSymbolAddress((void**)&wqh, g_wqh);
    cudaGetSymbolAddress((void**)&wql, g_wql);
    cudaGetSymbolAddress((void**)&wkh, g_wkh);
    cudaGetSymbolAddress((void**)&wkl, g_wkl);
    cudaGetSymbolAddress((void**)&wvh, g_wvh);
    cudaGetSymbolAddress((void**)&wvl, g_wvl);
    cudaGetSymbolAddress((void**)&woh, g_woh);
    cudaGetSymbolAddress((void**)&wol, g_wol);

    cudaFuncSetAttribute(gemm_tc, cudaFuncAttributeMaxDynamicSharedMemorySize,
                         GSMEM_TOTAL);

    const int n4 = ROWS * EMB / 4;
    split_bf16<<<(n4 + 255) / 256, 256>>>(x, xh, xl, n4);

    dim3 tg(EMB / 32, EMB / 32), tb(32, 8);
    tsplit_bf16<<<tg, tb>>>(Wq, wqh, wql);
    tsplit_bf16<<<tg, tb>>>(Wk, wkh, wkl);
    tsplit_bf16<<<tg, tb>>>(Wv, wvh, wvl);
    tsplit_bf16<<<tg, tb>>>(Wo, woh, wol);

    dim3 gg(EMB / 128, ROWS / 128); // (8, 64)
    gemm_tc<<<gg, 256, GSMEM_TOTAL>>>(xh, xl, wqh, wql, bq, qp);
    gemm_tc<<<gg, 256, GSMEM_TOTAL>>>(xh, xl, wkh, wkl, bk, kp);
    gemm_tc<<<gg, 256, GSMEM_TOTAL>>>(xh, xl, wvh, wvl, bv, vp);

    quantum_scan<<<ROWS, 256>>>(qp);
    quantum_scan<<<ROWS, 256>>>(kp);

    // Role swap per reference: query = quantum(k-proj), key = quantum(q-proj)
    dim3 ga(TT / 64, BB * NH); // (32, 64)
    flash_attn<<<ga, 256>>>(kp, qp, vp, ao);

    split_bf16<<<(n4 + 255) / 256, 256>>>(ao, aoh, aol, n4);
    gemm_tc<<<gg, 256, GSMEM_TOTAL>>>(aoh, aol, woh, wol, bo, out);
}

// round 4
// speedup vs baseline: 2.8490x; 2.1294x over previous
#include <cuda_runtime.h>
#include <cuda_bf16.h>
#include <cstdint>
#include <math.h>

#define EMB 1024
#define NH 16
#define HD 64
#define BB 4
#define TT 2048
#define ROWS (BB * TT) /* 8192 */

// ---------------- scratch (__device__ globals; no allocation allowed) -------
__device__ float g_qp[ROWS * EMB]; // fp32 x@Wq+bq (pre-quantum)
__device__ float g_kp[ROWS * EMB]; // fp32 x@Wk+bk (pre-quantum)

__device__ __nv_bfloat16 g_qh[ROWS * EMB], g_ql[ROWS * EMB]; // quantum(qproj)
__device__ __nv_bfloat16 g_kh[ROWS * EMB], g_kl[ROWS * EMB]; // quantum(kproj)
__device__ __nv_bfloat16 g_vh[ROWS * EMB], g_vl[ROWS * EMB]; // v projection
__device__ __nv_bfloat16 g_aoh[ROWS * EMB], g_aol[ROWS * EMB]; // attn out

__device__ __nv_bfloat16 g_xh[ROWS * EMB], g_xl[ROWS * EMB];   // x split
__device__ __nv_bfloat16 g_wqh[EMB * EMB], g_wql[EMB * EMB];   // W^T splits
__device__ __nv_bfloat16 g_wkh[EMB * EMB], g_wkl[EMB * EMB];
__device__ __nv_bfloat16 g_wvh[EMB * EMB], g_wvl[EMB * EMB];
__device__ __nv_bfloat16 g_woh[EMB * EMB], g_wol[EMB * EMB];

// ---------------- helpers ---------------------------------------------------
__device__ __forceinline__ uint32_t smem_u32(const void* p) {
    uint32_t a;
    asm("{ .reg .u64 t; cvta.to.shared.u64 t, %1; cvt.u32.u64 %0, t; }"
        : "=r"(a) : "l"(p));
    return a;
}

__device__ __forceinline__ void ldsm4(uint32_t* r, uint32_t addr) {
    asm volatile("ldmatrix.sync.aligned.m8n8.x4.shared.b16 {%0,%1,%2,%3}, [%4];"
                 : "=r"(r[0]), "=r"(r[1]), "=r"(r[2]), "=r"(r[3]) : "r"(addr));
}

__device__ __forceinline__ void ldsm4t(uint32_t* r, uint32_t addr) {
    asm volatile(
        "ldmatrix.sync.aligned.m8n8.x4.trans.shared.b16 {%0,%1,%2,%3}, [%4];"
        : "=r"(r[0]), "=r"(r[1]), "=r"(r[2]), "=r"(r[3]) : "r"(addr));
}

__device__ __forceinline__ void mma_bf16(float* d, const uint32_t* a,
                                         uint32_t b0, uint32_t b1) {
    asm volatile(
        "mma.sync.aligned.m16n8k16.row.col.f32.bf16.bf16.f32 "
        "{%0,%1,%2,%3}, {%4,%5,%6,%7}, {%8,%9}, {%0,%1,%2,%3};"
        : "+f"(d[0]), "+f"(d[1]), "+f"(d[2]), "+f"(d[3])
        : "r"(a[0]), "r"(a[1]), "r"(a[2]), "r"(a[3]), "r"(b0), "r"(b1));
}

__device__ __forceinline__ void mma_bf16_4(float* d, uint32_t a0, uint32_t a1,
                                           uint32_t a2, uint32_t a3,
                                           uint32_t b0, uint32_t b1) {
    asm volatile(
        "mma.sync.aligned.m16n8k16.row.col.f32.bf16.bf16.f32 "
        "{%0,%1,%2,%3}, {%4,%5,%6,%7}, {%8,%9}, {%0,%1,%2,%3};"
        : "+f"(d[0]), "+f"(d[1]), "+f"(d[2]), "+f"(d[3])
        : "r"(a0), "r"(a1), "r"(a2), "r"(a3), "r"(b0), "r"(b1));
}

__device__ __forceinline__ void cp16(uint32_t dst, const void* src) {
    asm volatile("cp.async.ca.shared.global [%0], [%1], 16;"
                 :: "r"(dst), "l"(src) : "memory");
}
__device__ __forceinline__ void cp_commit() {
    asm volatile("cp.async.commit_group;" ::: "memory");
}
__device__ __forceinline__ void cp_wait0() {
    asm volatile("cp.async.wait_group 0;" ::: "memory");
}

__device__ __forceinline__ uint32_t packbf2(float a, float b) {
    __nv_bfloat162 t = __halves2bfloat162(__float2bfloat16(a), __float2bfloat16(b));
    return *(uint32_t*)&t;
}

// ---------------------------------------------------------------------------
// split fp32 -> bf16 hi/lo
// ---------------------------------------------------------------------------
__global__ __launch_bounds__(256) void split_bf16(
    const float* __restrict__ src,
    __nv_bfloat16* __restrict__ hi, __nv_bfloat16* __restrict__ lo, int n4)
{
    int i = blockIdx.x * blockDim.x + threadIdx.x;
    if (i >= n4) return;
    float4 v = ((const float4*)src)[i];
    __nv_bfloat16 h0 = __float2bfloat16(v.x), h1 = __float2bfloat16(v.y);
    __nv_bfloat16 h2 = __float2bfloat16(v.z), h3 = __float2bfloat16(v.w);
    __nv_bfloat16 l0 = __float2bfloat16(v.x - __bfloat162float(h0));
    __nv_bfloat16 l1 = __float2bfloat16(v.y - __bfloat162float(h1));
    __nv_bfloat16 l2 = __float2bfloat16(v.z - __bfloat162float(h2));
    __nv_bfloat16 l3 = __float2bfloat16(v.w - __bfloat162float(h3));
    __nv_bfloat162* hp = (__nv_bfloat162*)hi;
    __nv_bfloat162* lp = (__nv_bfloat162*)lo;
    hp[i * 2 + 0] = __halves2bfloat162(h0, h1);
    hp[i * 2 + 1] = __halves2bfloat162(h2, h3);
    lp[i * 2 + 0] = __halves2bfloat162(l0, l1);
    lp[i * 2 + 1] = __halves2bfloat162(l2, l3);
}

// ---------------------------------------------------------------------------
// transpose + split: Wt[n][k] = W[k][n] as bf16 hi/lo  (1024x1024)
// ---------------------------------------------------------------------------
__global__ __launch_bounds__(256) void tsplit_bf16(
    const float* __restrict__ W,
    __nv_bfloat16* __restrict__ th, __nv_bfloat16* __restrict__ tl)
{
    __shared__ float s[32][33];
    int tx = threadIdx.x, ty = threadIdx.y; // (32, 8)
    int n0 = blockIdx.x * 32, k0 = blockIdx.y * 32;
#pragma unroll
    for (int j = 0; j < 4; j++)
        s[ty + 8 * j][tx] = W[(size_t)(k0 + ty + 8 * j) * EMB + n0 + tx];
    __syncthreads();
#pragma unroll
    for (int j = 0; j < 4; j++) {
        int n = n0 + ty + 8 * j, k = k0 + tx;
        float v = s[tx][ty + 8 * j];
        __nv_bfloat16 h = __float2bfloat16(v);
        th[(size_t)n * EMB + k] = h;
        tl[(size_t)n * EMB + k] = __float2bfloat16(v - __bfloat162float(h));
    }
}

// ---------------------------------------------------------------------------
// Tensor-core GEMM via mma.sync bf16 hi/lo split (from R3, passing).
// OUTMODE 0: fp32 C + bias. OUTMODE 1: bf16 hi/lo pair output + bias.
// ---------------------------------------------------------------------------
#define SROW 40
#define TILE_B (128 * SROW * 2)
#define STAGE_B (4 * TILE_B)
#define GSMEM_TOTAL (2 * STAGE_B)

template <int OUTMODE>
__global__ __launch_bounds__(256) void gemm_tc(
    const __nv_bfloat16* __restrict__ Ah, const __nv_bfloat16* __restrict__ Al,
    const __nv_bfloat16* __restrict__ Bh, const __nv_bfloat16* __restrict__ Bl,
    const float* __restrict__ bias, float* __restrict__ C,
    __nv_bfloat16* __restrict__ Ch, __nv_bfloat16* __restrict__ Cl)
{
    extern __shared__ char smem[];
    const int tid = threadIdx.x, wid = tid >> 5, L = tid & 31;
    const int bx = blockIdx.x, by = blockIdx.y;
    const uint32_t sb = smem_u32(smem);

    const int warp_m = (wid >> 2) * 64;
    const int warp_n = (wid & 3) * 32;

    const uint32_t a_off = (uint32_t)(warp_m + (L & 15)) * 80 + (L >> 4) * 16;
    const uint32_t b_off =
        (uint32_t)(warp_n + (L >> 4) * 8 + (L & 7)) * 80 + ((L >> 3) & 1) * 16;

    const int lr = tid >> 2, lc = tid & 3;
    const __nv_bfloat16* gA[2] = {Ah + (size_t)(by * 128 + lr) * EMB + lc * 8,
                                  Al + (size_t)(by * 128 + lr) * EMB + lc * 8};
    const __nv_bfloat16* gB[2] = {Bh + (size_t)(bx * 128 + lr) * EMB + lc * 8,
                                  Bl + (size_t)(bx * 128 + lr) * EMB + lc * 8};
    const uint32_t s_off0 = (uint32_t)lr * 80 + lc * 16;
    const uint32_t s_off1 = (uint32_t)(lr + 64) * 80 + lc * 16;

    float acc[4][4][4];
#pragma unroll
    for (int mt = 0; mt < 4; mt++)
#pragma unroll
        for (int nt = 0; nt < 4; nt++)
#pragma unroll
            for (int j = 0; j < 4; j++) acc[mt][nt][j] = 0.f;

#pragma unroll
    for (int t = 0; t < 2; t++) {
        char* dst = smem + t * TILE_B;
        *(uint4*)(dst + s_off0) = *(const uint4*)(gA[t]);
        *(uint4*)(dst + s_off1) = *(const uint4*)(gA[t] + 64 * EMB);
        char* dstB = smem + (2 + t) * TILE_B;
        *(uint4*)(dstB + s_off0) = *(const uint4*)(gB[t]);
        *(uint4*)(dstB + s_off1) = *(const uint4*)(gB[t] + 64 * EMB);
    }
    __syncthreads();

    const int NC = EMB / 32;
    uint4 stg[8];

    for (int kc = 0; kc < NC; ++kc) {
        const int cur = kc & 1;
        if (kc + 1 < NC) {
            const int k0 = (kc + 1) * 32;
#pragma unroll
            for (int t = 0; t < 2; t++) {
                stg[t * 2 + 0] = *(const uint4*)(gA[t] + k0);
                stg[t * 2 + 1] = *(const uint4*)(gA[t] + 64 * EMB + k0);
                stg[4 + t * 2 + 0] = *(const uint4*)(gB[t] + k0);
                stg[4 + t * 2 + 1] = *(const uint4*)(gB[t] + 64 * EMB + k0);
            }
        }

        const uint32_t st = sb + cur * STAGE_B;
#pragma unroll
        for (int ks = 0; ks < 2; ++ks) {
            uint32_t afh[4][4], afl[4][4], bfh[2][4], bfl[2][4];
#pragma unroll
            for (int mt = 0; mt < 4; mt++) {
                uint32_t ad = st + a_off + mt * (16 * 80) + ks * 32;
                ldsm4(afh[mt], ad);
                ldsm4(afl[mt], ad + TILE_B);
            }
#pragma unroll
            for (int np = 0; np < 2; np++) {
                uint32_t bd = st + 2 * TILE_B + b_off + np * (16 * 80) + ks * 32;
                ldsm4(bfh[np], bd);
                ldsm4(bfl[np], bd + TILE_B);
            }
#pragma unroll
            for (int mt = 0; mt < 4; mt++)
#pragma unroll
                for (int np = 0; np < 2; np++) {
                    mma_bf16(acc[mt][np * 2 + 0], afh[mt], bfh[np][0], bfh[np][1]);
                    mma_bf16(acc[mt][np * 2 + 0], afh[mt], bfl[np][0], bfl[np][1]);
                    mma_bf16(acc[mt][np * 2 + 0], afl[mt], bfh[np][0], bfh[np][1]);
                    mma_bf16(acc[mt][np * 2 + 1], afh[mt], bfh[np][2], bfh[np][3]);
                    mma_bf16(acc[mt][np * 2 + 1], afh[mt], bfl[np][2], bfl[np][3]);
                    mma_bf16(acc[mt][np * 2 + 1], afl[mt], bfh[np][2], bfh[np][3]);
                }
        }

        if (kc + 1 < NC) {
            __syncthreads();
            char* nb = smem + (cur ^ 1) * STAGE_B;
#pragma unroll
            for (int t = 0; t < 2; t++) {
                *(uint4*)(nb + t * TILE_B + s_off0) = stg[t * 2 + 0];
                *(uint4*)(nb + t * TILE_B + s_off1) = stg[t * 2 + 1];
                *(uint4*)(nb + (2 + t) * TILE_B + s_off0) = stg[4 + t * 2 + 0];
                *(uint4*)(nb + (2 + t) * TILE_B + s_off1) = stg[4 + t * 2 + 1];
            }
            __syncthreads();
        }
    }

    const int qr = L >> 2, qc = (L & 3) * 2;
#pragma unroll
    for (int mt = 0; mt < 4; mt++) {
#pragma unroll
        for (int nt = 0; nt < 4; nt++) {
            int col = bx * 128 + warp_n + nt * 8 + qc;
            float b0 = bias[col], b1 = bias[col + 1];
            int r0 = by * 128 + warp_m + mt * 16 + qr;
            float v00 = acc[mt][nt][0] + b0, v01 = acc[mt][nt][1] + b1;
            float v10 = acc[mt][nt][2] + b0, v11 = acc[mt][nt][3] + b1;
            if (OUTMODE == 0) {
                *(float2*)&C[(size_t)r0 * EMB + col] = make_float2(v00, v01);
                *(float2*)&C[(size_t)(r0 + 8) * EMB + col] = make_float2(v10, v11);
            } else {
                uint32_t h0 = packbf2(v00, v01);
                uint32_t h1 = packbf2(v10, v11);
                float r00 = v00 - __bfloat162float(__float2bfloat16(v00));
                float r01 = v01 - __bfloat162float(__float2bfloat16(v01));
                float r10 = v10 - __bfloat162float(__float2bfloat16(v10));
                float r11 = v11 - __bfloat162float(__float2bfloat16(v11));
                *(uint32_t*)&Ch[(size_t)r0 * EMB + col] = h0;
                *(uint32_t*)&Ch[(size_t)(r0 + 8) * EMB + col] = h1;
                *(uint32_t*)&Cl[(size_t)r0 * EMB + col] = packbf2(r00, r01);
                *(uint32_t*)&Cl[(size_t)(r0 + 8) * EMB + col] = packbf2(r10, r11);
            }
        }
    }
}

// ---------------------------------------------------------------------------
// quantum_layer: cumprod(cos(in)) rows of 1024 -> bf16 hi/lo outputs
// ---------------------------------------------------------------------------
__global__ __launch_bounds__(256) void quantum_scan(
    const float* __restrict__ in,
    __nv_bfloat16* __restrict__ oh, __nv_bfloat16* __restrict__ ol)
{
    __shared__ float s[256];
    int row = blockIdx.x;
    const float4* p = (const float4*)(in + (size_t)row * EMB);
    int t = threadIdx.x;

    float4 v = p[t];
    float c0 = cosf(v.x), c1 = cosf(v.y), c2 = cosf(v.z), c3 = cosf(v.w);
    float p0 = c0;
    float p1 = p0 * c1;
    float p2 = p1 * c2;
    float p3 = p2 * c3;

    s[t] = p3;
    __syncthreads();
    for (int off = 1; off < 256; off <<= 1) {
        float o = (t >= off) ? s[t - off] : 1.0f;
        __syncthreads();
        s[t] *= o;
        __syncthreads();
    }
    float pref = (t > 0) ? s[t - 1] : 1.0f;
    float f0 = pref * p0, f1 = pref * p1, f2 = pref * p2, f3 = pref * p3;

    uint32_t* hp = (uint32_t*)(oh + (size_t)row * EMB);
    uint32_t* lp = (uint32_t*)(ol + (size_t)row * EMB);
    hp[t * 2 + 0] = packbf2(f0, f1);
    hp[t * 2 + 1] = packbf2(f2, f3);
    float r0 = f0 - __bfloat162float(__float2bfloat16(f0));
    float r1 = f1 - __bfloat162float(__float2bfloat16(f1));
    float r2 = f2 - __bfloat162float(__float2bfloat16(f2));
    float r3 = f3 - __bfloat162float(__float2bfloat16(f3));
    lp[t * 2 + 0] = packbf2(r0, r1);
    lp[t * 2 + 1] = packbf2(r2, r3);
}

// ---------------------------------------------------------------------------
// Tensor-core flash attention, bf16 hi/lo splits on both GEMMs.
// CTA: 128 queries x one (b,h). 8 warps, each a 16-row stripe x full 64 keys.
// K tiles of 64 keys, cp.async double-buffered.
// SMEM rows stride 144 B (64 bf16 + pad) -> conflict-free ldmatrix.
// ---------------------------------------------------------------------------
#define FSTRIDE 144
#define FQ_B (128 * FSTRIDE)           /* 18432 per split */
#define FKV_B (64 * FSTRIDE)           /* 9216 per subtile */
#define FSTAGE_B (4 * FKV_B)           /* Kh,Kl,Vh,Vl */
#define FSMEM_TOTAL (2 * FQ_B + 2 * FSTAGE_B) /* 110592 */

__global__ __launch_bounds__(256) void flash_tc(
    const __nv_bfloat16* __restrict__ Qh_g, const __nv_bfloat16* __restrict__ Ql_g,
    const __nv_bfloat16* __restrict__ Kh_g, const __nv_bfloat16* __restrict__ Kl_g,
    const __nv_bfloat16* __restrict__ Vh_g, const __nv_bfloat16* __restrict__ Vl_g,
    __nv_bfloat16* __restrict__ Oh, __nv_bfloat16* __restrict__ Ol)
{
    extern __shared__ char smem[];
    const int tid = threadIdx.x, wid = tid >> 5, L = tid & 31;
    const int bh = blockIdx.y;
    const int b = bh >> 4, h = bh & 15;
    const int q0 = blockIdx.x * 128;
    const size_t rb = (size_t)b * TT;     // global row base
    const int cb = h * HD;                // global col base
    const uint32_t sb = smem_u32(smem);

    // ---- load Q tile (128 x 64, hi+lo) into SMEM ----
    {
        int r = tid >> 1, c = (tid & 1) * 4; // 512 uint4 per split? no: 128*64*2B/16 = 1024 chunks
    }
#pragma unroll
    for (int u = 0; u < 4; ++u) {
        int idx = tid + u * 256;       // 0..1023
        int r = idx >> 3, c = idx & 7; // r 0..127, c 0..7
        const size_t go = (rb + q0 + r) * EMB + cb + c * 8;
        *(uint4*)(smem + r * FSTRIDE + c * 16) = *(const uint4*)(Qh_g + go);
        *(uint4*)(smem + FQ_B + r * FSTRIDE + c * 16) = *(const uint4*)(Ql_g + go);
    }

    // ---- cp.async issue for K/V tile ----
    const __nv_bfloat16* kvsrc[4] = {Kh_g, Kl_g, Vh_g, Vl_g};
    auto issue_kv = [&](int key0, int stg) {
#pragma unroll
        for (int u = 0; u < 8; ++u) {
            int idx = tid + u * 256;                 // 0..2047
            int t = idx >> 9, rem = idx & 511;       // t: subtile
            int r = rem >> 3, c = rem & 7;           // r 0..63, c 0..7
            uint32_t dst = sb + 2 * FQ_B + stg * FSTAGE_B + t * FKV_B +
                           r * FSTRIDE + c * 16;
            cp16(dst, kvsrc[t] + (rb + key0 + r) * EMB + cb + c * 8);
        }
        cp_commit();
    };

    issue_kv(0, 0);
    __syncthreads(); // Q visible

    // ---- Q fragments in registers (once) ----
    const uint32_t qa_off = (uint32_t)(wid * 16 + (L & 15)) * FSTRIDE + (L >> 4) * 16;
    uint32_t qfh[4][4], qfl[4][4];
#pragma unroll
    for (int kk = 0; kk < 4; ++kk) {
        ldsm4(qfh[kk], sb + qa_off + kk * 32);
        ldsm4(qfl[kk], sb + FQ_B + qa_off + kk * 32);
    }

    const uint32_t kb_off =
        (uint32_t)((L >> 4) * 8 + (L & 7)) * FSTRIDE + ((L >> 3) & 1) * 16;
    // V trans per-lane address (within V subtile): key row + d col
    const uint32_t vt_key = ((L >> 3) & 1) * 8 + (L & 7);
    const uint32_t vt_d = (L >> 4) * 8;

    float mA = -INFINITY, mB = -INFINITY, lA = 0.f, lB = 0.f;
    float oacc[8][4];
#pragma unroll
    for (int nt = 0; nt < 8; nt++)
#pragma unroll
        for (int j = 0; j < 4; j++) oacc[nt][j] = 0.f;

    const int NT = TT / 64; // 32
    for (int kt = 0; kt < NT; ++kt) {
        const int cur = kt & 1;
        cp_wait0();
        __syncthreads();
        if (kt + 1 < NT) issue_kv((kt + 1) * 64, cur ^ 1);

        const uint32_t Kh_s = sb + 2 * FQ_B + cur * FSTAGE_B;
        const uint32_t Kl_s = Kh_s + FKV_B;
        const uint32_t Vh_s = Kh_s + 2 * FKV_B;
        const uint32_t Vl_s = Kh_s + 3 * FKV_B;

        // ---- S = Q @ K^T (3-term split) ----
        float sacc[8][4];
#pragma unroll
        for (int nt = 0; nt < 8; nt++)
#pragma unroll
            for (int j = 0; j < 4; j++) sacc[nt][j] = 0.f;

#pragma unroll
        for (int kk = 0; kk < 4; ++kk) {
            uint32_t kh[4][4], kl[4][4];
#pragma unroll
            for (int np = 0; np < 4; np++) {
                uint32_t bd = kb_off + np * (16 * FSTRIDE) + kk * 32;
                ldsm4(kh[np], Kh_s + bd);
                ldsm4(kl[np], Kl_s + bd);
            }
#pragma unroll
            for (int np = 0; np < 4; np++) {
                mma_bf16(sacc[np * 2 + 0], qfh[kk], kh[np][0], kh[np][1]);
                mma_bf16(sacc[np * 2 + 0], qfh[kk], kl[np][0], kl[np][1]);
                mma_bf16(sacc[np * 2 + 0], qfl[kk], kh[np][0], kh[np][1]);
                mma_bf16(sacc[np * 2 + 1], qfh[kk], kh[np][2], kh[np][3]);
                mma_bf16(sacc[np * 2 + 1], qfh[kk], kl[np][2], kl[np][3]);
                mma_bf16(sacc[np * 2 + 1], qfl[kk], kh[np][2], kh[np][3]);
            }
        }

        // ---- online softmax (warp-local per 16-row stripe) ----
        float mxA = -INFINITY, mxB = -INFINITY;
#pragma unroll
        for (int nt = 0; nt < 8; nt++) {
            sacc[nt][0] *= 0.125f; sacc[nt][1] *= 0.125f;
            sacc[nt][2] *= 0.125f; sacc[nt][3] *= 0.125f;
            mxA = fmaxf(mxA, fmaxf(sacc[nt][0], sacc[nt][1]));
            mxB = fmaxf(mxB, fmaxf(sacc[nt][2], sacc[nt][3]));
        }
        mxA = fmaxf(mxA, __shfl_xor_sync(0xffffffffu, mxA, 1));
        mxA = fmaxf(mxA, __shfl_xor_sync(0xffffffffu, mxA, 2));
        mxB = fmaxf(mxB, __shfl_xor_sync(0xffffffffu, mxB, 1));
        mxB = fmaxf(mxB, __shfl_xor_sync(0xffffffffu, mxB, 2));

        float mnA = fmaxf(mA, mxA), mnB = fmaxf(mB, mxB);
        float corrA = __expf(mA - mnA), corrB = __expf(mB - mnB);

        uint32_t ph01[8], ph23[8], pl01[8], pl23[8];
        float sumA = 0.f, sumB = 0.f;
#pragma unroll
        for (int nt = 0; nt < 8; nt++) {
            float p0 = __expf(sacc[nt][0] - mnA);
            float p1 = __expf(sacc[nt][1] - mnA);
            float p2 = __expf(sacc[nt][2] - mnB);
            float p3 = __expf(sacc[nt][3] - mnB);
            sumA += p0 + p1;
            sumB += p2 + p3;
            ph01[nt] = packbf2(p0, p1);
            ph23[nt] = packbf2(p2, p3);
            float r0 = p0 - __bfloat162float(__float2bfloat16(p0));
            float r1 = p1 - __bfloat162float(__float2bfloat16(p1));
            float r2 = p2 - __bfloat162float(__float2bfloat16(p2));
            float r3 = p3 - __bfloat162float(__float2bfloat16(p3));
            pl01[nt] = packbf2(r0, r1);
            pl23[nt] = packbf2(r2, r3);
        }
        sumA += __shfl_xor_sync(0xffffffffu, sumA, 1);
        sumA += __shfl_xor_sync(0xffffffffu, sumA, 2);
        sumB += __shfl_xor_sync(0xffffffffu, sumB, 1);
        sumB += __shfl_xor_sync(0xffffffffu, sumB, 2);

        lA = lA * corrA + sumA; mA = mnA;
        lB = lB * corrB + sumB; mB = mnB;
#pragma unroll
        for (int nt = 0; nt < 8; nt++) {
            oacc[nt][0] *= corrA; oacc[nt][1] *= corrA;
            oacc[nt][2] *= corrB; oacc[nt][3] *= corrB;
        }

        // ---- O += P @ V (3-term split; V via ldmatrix.trans) ----
#pragma unroll
        for (int kk = 0; kk < 4; ++kk) {
            uint32_t vkey = (vt_key + kk * 16) * FSTRIDE;
#pragma unroll
            for (int ntp = 0; ntp < 4; ++ntp) {
                uint32_t va = vkey + (vt_d + ntp * 16) * 2;
                uint32_t vh[4], vl[4];
                ldsm4t(vh, Vh_s + va);
                ldsm4t(vl, Vl_s + va);
                int n0 = ntp * 2, n1 = ntp * 2 + 1;
                mma_bf16_4(oacc[n0], ph01[2 * kk], ph23[2 * kk],
                           ph01[2 * kk + 1], ph23[2 * kk + 1], vh[0], vh[1]);
                mma_bf16_4(oacc[n0], ph01[2 * kk], ph23[2 * kk],
                           ph01[2 * kk + 1], ph23[2 * kk + 1], vl[0], vl[1]);
                mma_bf16_4(oacc[n0], pl01[2 * kk], pl23[2 * kk],
                           pl01[2 * kk + 1], pl23[2 * kk + 1], vh[0], vh[1]);
                mma_bf16_4(oacc[n1], ph01[2 * kk], ph23[2 * kk],
                           ph01[2 * kk + 1], ph23[2 * kk + 1], vh[2], vh[3]);
                mma_bf16_4(oacc[n1], ph01[2 * kk], ph23[2 * kk],
                           ph01[2 * kk + 1], ph23[2 * kk + 1], vl[2], vl[3]);
                mma_bf16_4(oacc[n1], pl01[2 * kk], pl23[2 * kk],
                           pl01[2 * kk + 1], pl23[2 * kk + 1], vh[2], vh[3]);
            }
        }
    }

    // ---- epilogue: normalize, write bf16 hi/lo combined-heads layout ----
    float invA = 1.0f / lA, invB = 1.0f / lB;
    const size_t rowA = (rb + q0 + wid * 16 + (L >> 2)) * EMB;
    const size_t rowB = rowA + 8 * EMB;
#pragma unroll
    for (int nt = 0; nt < 8; nt++) {
        int col = cb + nt * 8 + (L & 3) * 2;
        float v0 = oacc[nt][0] * invA, v1 = oacc[nt][1] * invA;
        float v2 = oacc[nt][2] * invB, v3 = oacc[nt][3] * invB;
        *(uint32_t*)&Oh[rowA + col] = packbf2(v0, v1);
        *(uint32_t*)&Oh[rowB + col] = packbf2(v2, v3);
        float r0 = v0 - __bfloat162float(__float2bfloat16(v0));
        float r1 = v1 - __bfloat162float(__float2bfloat16(v1));
        float r2 = v2 - __bfloat162float(__float2bfloat16(v2));
        float r3 = v3 - __bfloat162float(__float2bfloat16(v3));
        *(uint32_t*)&Ol[rowA + col] = packbf2(r0, r1);
        *(uint32_t*)&Ol[rowB + col] = packbf2(r2, r3);
    }
}

// ---------------------------------------------------------------------------
extern "C" void kernel_launch(void* const* d_in, const int* in_sizes, int n_in,
                              void* d_out, int out_size)
{
    const float* x  = (const float*)d_in[0];
    const float* Wq = (const float*)d_in[1];
    const float* bq = (const float*)d_in[2];
    const float* Wk = (const float*)d_in[3];
    const float* bk = (const float*)d_in[4];
    const float* Wv = (const float*)d_in[5];
    const float* bv = (const float*)d_in[6];
    const float* Wo = (const float*)d_in[7];
    const float* bo = (const float*)d_in[8];
    float* out = (float*)d_out;

    float *qp, *kp;
    cudaGetSymbolAddress((void**)&qp, g_qp);
    cudaGetSymbolAddress((void**)&kp, g_kp);

    __nv_bfloat16 *qh, *ql, *kh, *kl, *vh, *vl, *aoh, *aol, *xh, *xl;
    __nv_bfloat16 *wqh, *wql, *wkh, *wkl, *wvh, *wvl, *woh, *wol;
    cudaGetSymbolAddress((void**)&qh, g_qh);
    cudaGetSymbolAddress((void**)&ql, g_ql);
    cudaGetSymbolAddress((void**)&kh, g_kh);
    cudaGetSymbolAddress((void**)&kl, g_kl);
    cudaGetSymbolAddress((void**)&vh, g_vh);
    cudaGetSymbolAddress((void**)&vl, g_vl);
    cudaGetSymbolAddress((void**)&aoh, g_aoh);
    cudaGetSymbolAddress((void**)&aol, g_aol);
    cudaGetSymbolAddress((void**)&xh, g_xh);
    cudaGetSymbolAddress((void**)&xl, g_xl);
    cudaGetSymbolAddress((void**)&wqh, g_wqh);
    cudaGetSymbolAddress((void**)&wql, g_wql);
    cudaGetSymbolAddress((void**)&wkh, g_wkh);
    cudaGetSymbolAddress((void**)&wkl, g_wkl);
    cudaGetSymbolAddress((void**)&wvh, g_wvh);
    cudaGetSymbolAddress((void**)&wvl, g_wvl);
    cudaGetSymbolAddress((void**)&woh, g_woh);
    cudaGetSymbolAddress((void**)&wol, g_wol);

    cudaFuncSetAttribute(gemm_tc<0>, cudaFuncAttributeMaxDynamicSharedMemorySize,
                         GSMEM_TOTAL);
    cudaFuncSetAttribute(gemm_tc<1>, cudaFuncAttributeMaxDynamicSharedMemorySize,
                         GSMEM_TOTAL);
    cudaFuncSetAttribute(flash_tc, cudaFuncAttributeMaxDynamicSharedMemorySize,
                         FSMEM_TOTAL);

    const int n4 = ROWS * EMB / 4;
    split_bf16<<<(n4 + 255) / 256, 256>>>(x, xh, xl, n4);

    dim3 tg(EMB / 32, EMB / 32), tb(32, 8);
    tsplit_bf16<<<tg, tb>>>(Wq, wqh, wql);
    tsplit_bf16<<<tg, tb>>>(Wk, wkh, wkl);
    tsplit_bf16<<<tg, tb>>>(Wv, wvh, wvl);
    tsplit_bf16<<<tg, tb>>>(Wo, woh, wol);

    dim3 gg(EMB / 128, ROWS / 128); // (8, 64)
    gemm_tc<0><<<gg, 256, GSMEM_TOTAL>>>(xh, xl, wqh, wql, bq, qp, nullptr, nullptr);
    gemm_tc<0><<<gg, 256, GSMEM_TOTAL>>>(xh, xl, wkh, wkl, bk, kp, nullptr, nullptr);
    gemm_tc<1><<<gg, 256, GSMEM_TOTAL>>>(xh, xl, wvh, wvl, bv, nullptr, vh, vl);

    quantum_scan<<<ROWS, 256>>>(qp, qh, ql);
    quantum_scan<<<ROWS, 256>>>(kp, kh, kl);

    // Role swap per reference: query = quantum(k-proj), key = quantum(q-proj)
    dim3 ga(TT / 128, BB * NH); // (16, 64)
    flash_tc<<<ga, 256, FSMEM_TOTAL>>>(kh, kl, qh, ql, vh, vl, aoh, aol);

    gemm_tc<0><<<gg, 256, GSMEM_TOTAL>>>(aoh, aol, woh, wol, bo, out, nullptr, nullptr);
}